// round 1
// baseline (speedup 1.0000x reference)
#include <cuda_runtime.h>
#include <math.h>

// Problem constants
static constexpr int BATCH = 4;
static constexpr int NSEQ  = 4096;
static constexpr int DIMC  = 768;   // input dim == head dim
static constexpr int H3    = 3 * DIMC;  // 2304

// Scratch: packed qkv [B, N, 3H] and scores [B, N, N]
__device__ float g_qkv[(size_t)BATCH * NSEQ * H3];          // ~151 MB
__device__ float g_S[(size_t)BATCH * NSEQ * NSEQ];          // ~268 MB

// ---------------------------------------------------------------------------
// Generic tiled SGEMM: C = alpha * A @ op(B) (+ bias)
//   A: [M, K] row-major, lda
//   B: TRANS_B ? [N, K] (row-major, we compute A @ B^T) : [K, N]
//   C: [M, N] row-major, ldc
// Block tile 128x128, K-tile 8, 256 threads, 8x8 per-thread microtile.
// All dims in this problem are multiples of the tile sizes -> no bounds checks.
// ---------------------------------------------------------------------------
template <bool TRANS_B, bool BIAS>
__global__ __launch_bounds__(256)
void sgemm_kernel(const float* __restrict__ A, const float* __restrict__ B,
                  const float* __restrict__ bias, float* __restrict__ C,
                  int M, int N, int K, int lda, int ldb, int ldc,
                  size_t sA, size_t sB, size_t sC, float alpha)
{
    __shared__ float As[8][128];
    __shared__ float Bs[8][128];

    A += (size_t)blockIdx.z * sA;
    B += (size_t)blockIdx.z * sB;
    C += (size_t)blockIdx.z * sC;

    const int bm = blockIdx.y * 128;
    const int bn = blockIdx.x * 128;
    const int tid = threadIdx.x;
    const int tx = tid & 15;        // 0..15  -> 8 cols each
    const int ty = tid >> 4;        // 0..15  -> 8 rows each

    // A tile load mapping: 128 rows x 8 cols, one float4 per thread along K
    const int arow = tid >> 1;          // 0..127
    const int acol = (tid & 1) * 4;     // 0 or 4
    // B tile load mapping
    const int brow_t = tid >> 1;        // TRANS_B: 0..127 (N rows)
    const int bcol_t = (tid & 1) * 4;   // TRANS_B: K offset
    const int brow_n = tid >> 5;        // NN: 0..7 (K rows)
    const int bcol_n = (tid & 31) * 4;  // NN: 0..124 (N offset)

    float acc[8][8];
#pragma unroll
    for (int i = 0; i < 8; i++)
#pragma unroll
        for (int j = 0; j < 8; j++) acc[i][j] = 0.0f;

    for (int k0 = 0; k0 < K; k0 += 8) {
        // Load A 128x8 -> As[k][m] (transposed)
        {
            float4 a = *(const float4*)(A + (size_t)(bm + arow) * lda + (k0 + acol));
            As[acol + 0][arow] = a.x;
            As[acol + 1][arow] = a.y;
            As[acol + 2][arow] = a.z;
            As[acol + 3][arow] = a.w;
        }
        // Load B -> Bs[k][n]
        if (TRANS_B) {
            float4 b = *(const float4*)(B + (size_t)(bn + brow_t) * ldb + (k0 + bcol_t));
            Bs[bcol_t + 0][brow_t] = b.x;
            Bs[bcol_t + 1][brow_t] = b.y;
            Bs[bcol_t + 2][brow_t] = b.z;
            Bs[bcol_t + 3][brow_t] = b.w;
        } else {
            float4 b = *(const float4*)(B + (size_t)(k0 + brow_n) * ldb + (bn + bcol_n));
            *(float4*)&Bs[brow_n][bcol_n] = b;
        }
        __syncthreads();

#pragma unroll
        for (int k = 0; k < 8; k++) {
            float4 a0 = *(const float4*)&As[k][ty * 8];
            float4 a1 = *(const float4*)&As[k][ty * 8 + 4];
            float4 b0 = *(const float4*)&Bs[k][tx * 8];
            float4 b1 = *(const float4*)&Bs[k][tx * 8 + 4];
            float ra[8] = {a0.x, a0.y, a0.z, a0.w, a1.x, a1.y, a1.z, a1.w};
            float rb[8] = {b0.x, b0.y, b0.z, b0.w, b1.x, b1.y, b1.z, b1.w};
#pragma unroll
            for (int i = 0; i < 8; i++)
#pragma unroll
                for (int j = 0; j < 8; j++)
                    acc[i][j] = fmaf(ra[i], rb[j], acc[i][j]);
        }
        __syncthreads();
    }

    // Epilogue
#pragma unroll
    for (int i = 0; i < 8; i++) {
        const int row = bm + ty * 8 + i;
#pragma unroll
        for (int j = 0; j < 8; j += 4) {
            const int col = bn + tx * 8 + j;
            float4 v;
            v.x = alpha * acc[i][j + 0];
            v.y = alpha * acc[i][j + 1];
            v.z = alpha * acc[i][j + 2];
            v.w = alpha * acc[i][j + 3];
            if (BIAS) {
                float4 bb = *(const float4*)(bias + col);
                v.x += bb.x; v.y += bb.y; v.z += bb.z; v.w += bb.w;
            }
            *(float4*)(C + (size_t)row * ldc + col) = v;
        }
    }
}

// ---------------------------------------------------------------------------
// Row softmax over g_S: rows = BATCH*NSEQ, cols = NSEQ. One block per row,
// row resident in registers (16 elems/thread @ 256 threads).
// ---------------------------------------------------------------------------
__global__ __launch_bounds__(256)
void softmax_kernel(float* __restrict__ S)
{
    const size_t row = blockIdx.x;
    float* p = S + row * (size_t)NSEQ;
    const int tid = threadIdx.x;

    float v[16];
    float m = -INFINITY;
#pragma unroll
    for (int i = 0; i < 16; i++) {
        v[i] = p[tid + i * 256];
        m = fmaxf(m, v[i]);
    }
#pragma unroll
    for (int o = 16; o > 0; o >>= 1)
        m = fmaxf(m, __shfl_xor_sync(0xFFFFFFFFu, m, o));

    __shared__ float redm[8];
    __shared__ float reds[8];
    if ((tid & 31) == 0) redm[tid >> 5] = m;
    __syncthreads();
    float mrow = redm[0];
#pragma unroll
    for (int w = 1; w < 8; w++) mrow = fmaxf(mrow, redm[w]);

    float s = 0.0f;
#pragma unroll
    for (int i = 0; i < 16; i++) {
        v[i] = __expf(v[i] - mrow);
        s += v[i];
    }
#pragma unroll
    for (int o = 16; o > 0; o >>= 1)
        s += __shfl_xor_sync(0xFFFFFFFFu, s, o);
    if ((tid & 31) == 0) reds[tid >> 5] = s;
    __syncthreads();
    float tot = 0.0f;
#pragma unroll
    for (int w = 0; w < 8; w++) tot += reds[w];
    const float inv = 1.0f / tot;

#pragma unroll
    for (int i = 0; i < 16; i++)
        p[tid + i * 256] = v[i] * inv;
}

// ---------------------------------------------------------------------------
extern "C" void kernel_launch(void* const* d_in, const int* in_sizes, int n_in,
                              void* d_out, int out_size)
{
    const float* x = (const float*)d_in[0];   // [4, 4096, 768]
    const float* W = (const float*)d_in[1];   // [768, 2304]
    const float* b = (const float*)d_in[2];   // [2304]
    float* out = (float*)d_out;               // [4, 4096, 768]

    float* qkv = nullptr;
    float* S = nullptr;
    cudaGetSymbolAddress((void**)&qkv, g_qkv);
    cudaGetSymbolAddress((void**)&S, g_S);

    const size_t qkvBatchStride = (size_t)NSEQ * H3;       // 4096*2304
    const size_t sBatchStride   = (size_t)NSEQ * NSEQ;     // 4096*4096
    const size_t oBatchStride   = (size_t)NSEQ * DIMC;     // 4096*768

    // 1) qkv = x @ W + b : M=16384 (B*N folded), N=2304, K=768, NN + bias
    {
        dim3 grid(H3 / 128, (BATCH * NSEQ) / 128, 1);
        sgemm_kernel<false, true><<<grid, 256>>>(
            x, W, b, qkv,
            BATCH * NSEQ, H3, DIMC,
            DIMC, H3, H3,
            0, 0, 0, 1.0f);
    }

    // 2) S = Q @ K^T * (1/sqrt(768)) per batch : M=N=4096, K=768, NT
    {
        dim3 grid(NSEQ / 128, NSEQ / 128, BATCH);
        const float alpha = 1.0f / sqrtf((float)DIMC);
        sgemm_kernel<true, false><<<grid, 256>>>(
            qkv /*Q at col 0*/, qkv + DIMC /*K at col 768*/, nullptr, S,
            NSEQ, NSEQ, DIMC,
            H3, H3, NSEQ,
            qkvBatchStride, qkvBatchStride, sBatchStride, alpha);
    }

    // 3) softmax rows of S
    softmax_kernel<<<BATCH * NSEQ, 256>>>(S);

    // 4) out = P @ V per batch : M=4096, N=768, K=4096, NN
    {
        dim3 grid(DIMC / 128, NSEQ / 128, BATCH);
        sgemm_kernel<false, false><<<grid, 256>>>(
            S, qkv + 2 * DIMC /*V at col 1536*/, nullptr, out,
            NSEQ, DIMC, NSEQ,
            NSEQ, H3, DIMC,
            sBatchStride, qkvBatchStride, oBatchStride, 1.0f);
    }
}

// round 3
// speedup vs baseline: 3.0894x; 3.0894x over previous
#include <cuda_runtime.h>
#include <math.h>
#include <stdint.h>

// ---------------------------------------------------------------------------
// Problem constants
// ---------------------------------------------------------------------------
static constexpr int BATCH = 4;
static constexpr int NSEQ  = 4096;
static constexpr int DIMC  = 768;       // input dim == head dim
static constexpr int H3    = 3 * DIMC;  // 2304

// Scratch
__device__ float g_x[(size_t)BATCH * NSEQ * DIMC];            // ~50 MB (tf32-rounded x)
__device__ float g_qkv[(size_t)BATCH * NSEQ * H3];            // ~151 MB
__device__ float g_S[(size_t)BATCH * NSEQ * NSEQ];            // ~268 MB
__device__ float g_Wt[(size_t)H3 * DIMC];                     // ~7 MB  (W^T, tf32-rounded)
__device__ float g_Vt[(size_t)BATCH * DIMC * NSEQ];           // ~50 MB (V^T per batch)

// ---------------------------------------------------------------------------
// Helpers
// ---------------------------------------------------------------------------
__device__ __forceinline__ float round_tf32(float x) {
    uint32_t u;
    asm("cvt.rna.tf32.f32 %0, %1;" : "=r"(u) : "f"(x));
    return __uint_as_float(u);
}

__device__ __forceinline__ uint32_t smem_to_u32(const void* p) {
    uint32_t a;
    asm("{ .reg .u64 t; cvta.to.shared.u64 t, %1; cvt.u32.u64 %0, t; }"
        : "=r"(a) : "l"(p));
    return a;
}

__device__ __forceinline__ void cp_async16(uint32_t smem_addr, const void* gptr) {
    asm volatile("cp.async.cg.shared.global [%0], [%1], 16;"
                 :: "r"(smem_addr), "l"(gptr));
}

__device__ __forceinline__ void mma_tf32(float* d, const uint32_t* a, const uint32_t* b) {
    asm volatile(
        "mma.sync.aligned.m16n8k8.row.col.f32.tf32.tf32.f32 "
        "{%0,%1,%2,%3}, {%4,%5,%6,%7}, {%8,%9}, {%0,%1,%2,%3};"
        : "+f"(d[0]), "+f"(d[1]), "+f"(d[2]), "+f"(d[3])
        : "r"(a[0]), "r"(a[1]), "r"(a[2]), "r"(a[3]), "r"(b[0]), "r"(b[1]));
}

// ---------------------------------------------------------------------------
// tf32 mma.sync NT GEMM: C[M,N] = alpha * A[M,K] @ B[N,K]^T (+ bias[N])
// A, B K-major. Tile 128x128x32, 256 threads (8 warps, warp tile 64x32),
// 4-stage cp.async pipeline. Smem row stride 36 floats (conflict-free).
// Grid: (N/128, M/128, batch). Operands must be tf32-representable already.
// ---------------------------------------------------------------------------
static constexpr int STAGES = 4;
static constexpr int SROW = 36;                       // floats per smem row
static constexpr int STAGE_FLOATS = 128 * SROW;       // 4608
static constexpr int STAGE_BYTES = STAGE_FLOATS * 4;  // 18432
static constexpr uint32_t GEMM_DYNSMEM = 2 * STAGES * STAGE_BYTES;  // 147456

template <bool BIAS, bool ROUND>
__global__ __launch_bounds__(256)
void tc_gemm_nt(const float* __restrict__ A, const float* __restrict__ B,
                const float* __restrict__ bias, float* __restrict__ C,
                int K, int lda, int ldb, int ldc,
                size_t sA, size_t sB, size_t sC, float alpha)
{
    extern __shared__ float smem[];   // [STAGES][128][36] for A, then for B

    const int tid = threadIdx.x;
    const int lane = tid & 31;
    const int wid = tid >> 5;
    const int warp_m = wid & 1;       // 0..1
    const int warp_n = wid >> 1;      // 0..3
    const int bm = blockIdx.y * 128;
    const int bn = blockIdx.x * 128;

    const float* Abase = A + blockIdx.z * sA + (size_t)bm * lda;
    const float* Bbase = B + blockIdx.z * sB + (size_t)bn * ldb;
    C += blockIdx.z * sC;

    const uint32_t smem_u = smem_to_u32(smem);
    const uint32_t smemB_u = smem_u + STAGES * STAGE_BYTES;

    // Producer mapping: thread -> (row, 16B chunk); 32 rows per pass, 4 passes
    const int rowL = tid >> 3;        // 0..31
    const int colL = (tid & 7) * 4;   // 0,4,..,28

    const int niter = K >> 5;

    auto issue = [&](int it) {
        if (it < niter) {
            const int s = it & (STAGES - 1);
            const uint32_t dA = smem_u  + s * STAGE_BYTES;
            const uint32_t dB = smemB_u + s * STAGE_BYTES;
            const int kofs = it * 32 + colL;
#pragma unroll
            for (int p = 0; p < 4; p++) {
                const int r = rowL + 32 * p;
                const uint32_t so = (uint32_t)(r * SROW + colL) * 4u;
                cp_async16(dA + so, Abase + (size_t)r * lda + kofs);
                cp_async16(dB + so, Bbase + (size_t)r * ldb + kofs);
            }
        }
        asm volatile("cp.async.commit_group;" ::: "memory");
    };

    // Prologue: stages 0..2
    issue(0); issue(1); issue(2);

    float acc[4][4][4];
#pragma unroll
    for (int mi = 0; mi < 4; mi++)
#pragma unroll
        for (int ni = 0; ni < 4; ni++)
#pragma unroll
            for (int j = 0; j < 4; j++) acc[mi][ni][j] = 0.0f;

    const int mrow = warp_m * 64 + (lane >> 2);
    const int nrow = warp_n * 32 + (lane >> 2);
    const int kc_base = lane & 3;

    for (int it = 0; it < niter; ++it) {
        asm volatile("cp.async.wait_group 2;" ::: "memory");
        __syncthreads();
        issue(it + 3);

        const int s = it & (STAGES - 1);
        const float* As_s = smem + s * STAGE_FLOATS;
        const float* Bs_s = smem + STAGES * STAGE_FLOATS + s * STAGE_FLOATS;

#pragma unroll
        for (int ks = 0; ks < 4; ks++) {
            const int kc = ks * 8 + kc_base;
            uint32_t afr[4][4];
            uint32_t bfr[4][2];
#pragma unroll
            for (int mi = 0; mi < 4; mi++) {
                const int r = mrow + mi * 16;
                afr[mi][0] = __float_as_uint(As_s[r * SROW + kc]);
                afr[mi][1] = __float_as_uint(As_s[(r + 8) * SROW + kc]);
                afr[mi][2] = __float_as_uint(As_s[r * SROW + kc + 4]);
                afr[mi][3] = __float_as_uint(As_s[(r + 8) * SROW + kc + 4]);
            }
#pragma unroll
            for (int ni = 0; ni < 4; ni++) {
                const int rn = nrow + ni * 8;
                bfr[ni][0] = __float_as_uint(Bs_s[rn * SROW + kc]);
                bfr[ni][1] = __float_as_uint(Bs_s[rn * SROW + kc + 4]);
            }
#pragma unroll
            for (int mi = 0; mi < 4; mi++)
#pragma unroll
                for (int ni = 0; ni < 4; ni++)
                    mma_tf32(acc[mi][ni], afr[mi], bfr[ni]);
        }
    }

    // Epilogue
    const int erow = bm + warp_m * 64 + (lane >> 2);
    const int ecol = bn + warp_n * 32 + (lane & 3) * 2;
#pragma unroll
    for (int mi = 0; mi < 4; mi++) {
#pragma unroll
        for (int ni = 0; ni < 4; ni++) {
            const int m0 = erow + mi * 16;
            const int n0 = ecol + ni * 8;
            float v0 = acc[mi][ni][0] * alpha;
            float v1 = acc[mi][ni][1] * alpha;
            float v2 = acc[mi][ni][2] * alpha;
            float v3 = acc[mi][ni][3] * alpha;
            if (BIAS) {
                const float b0 = bias[n0], b1 = bias[n0 + 1];
                v0 += b0; v1 += b1; v2 += b0; v3 += b1;
            }
            if (ROUND) {
                v0 = round_tf32(v0); v1 = round_tf32(v1);
                v2 = round_tf32(v2); v3 = round_tf32(v3);
            }
            *(float2*)(C + (size_t)m0 * ldc + n0)       = make_float2(v0, v1);
            *(float2*)(C + (size_t)(m0 + 8) * ldc + n0) = make_float2(v2, v3);
        }
    }
}

// ---------------------------------------------------------------------------
// Round-to-tf32 copy: dst[i] = tf32(src[i])
// ---------------------------------------------------------------------------
__global__ __launch_bounds__(256)
void round_copy_kernel(const float* __restrict__ src, float* __restrict__ dst, size_t n4)
{
    const size_t stride = (size_t)gridDim.x * 256;
    for (size_t i = blockIdx.x * 256ull + threadIdx.x; i < n4; i += stride) {
        float4 v = ((const float4*)src)[i];
        v.x = round_tf32(v.x); v.y = round_tf32(v.y);
        v.z = round_tf32(v.z); v.w = round_tf32(v.w);
        ((float4*)dst)[i] = v;
    }
}

// ---------------------------------------------------------------------------
// Tiled transpose: out[c, r] = op(in[r, c]); optional tf32 rounding.
// ---------------------------------------------------------------------------
template <bool ROUND>
__global__ __launch_bounds__(256)
void transpose_kernel(const float* __restrict__ in, float* __restrict__ out,
                      int ld_in, int ld_out, size_t sIn, size_t sOut)
{
    __shared__ float tile[32][33];
    in  += blockIdx.z * sIn;
    out += blockIdx.z * sOut;
    const int r0 = blockIdx.y * 32;
    const int c0 = blockIdx.x * 32;
    const int tx = threadIdx.x;
    const int ty = threadIdx.y;
#pragma unroll
    for (int i = 0; i < 32; i += 8) {
        float v = in[(size_t)(r0 + ty + i) * ld_in + c0 + tx];
        tile[ty + i][tx] = ROUND ? round_tf32(v) : v;
    }
    __syncthreads();
#pragma unroll
    for (int i = 0; i < 32; i += 8)
        out[(size_t)(c0 + ty + i) * ld_out + r0 + tx] = tile[tx][ty + i];
}

// ---------------------------------------------------------------------------
// Row softmax over g_S (rows = BATCH*NSEQ, cols = NSEQ); output tf32-rounded.
// ---------------------------------------------------------------------------
__global__ __launch_bounds__(256)
void softmax_kernel(float* __restrict__ S)
{
    const size_t row = blockIdx.x;
    float* p = S + row * (size_t)NSEQ;
    const int tid = threadIdx.x;

    float v[16];
    float m = -INFINITY;
#pragma unroll
    for (int i = 0; i < 16; i++) {
        v[i] = p[tid + i * 256];
        m = fmaxf(m, v[i]);
    }
#pragma unroll
    for (int o = 16; o > 0; o >>= 1)
        m = fmaxf(m, __shfl_xor_sync(0xFFFFFFFFu, m, o));

    __shared__ float redm[8];
    __shared__ float reds[8];
    if ((tid & 31) == 0) redm[tid >> 5] = m;
    __syncthreads();
    float mrow = redm[0];
#pragma unroll
    for (int w = 1; w < 8; w++) mrow = fmaxf(mrow, redm[w]);

    float s = 0.0f;
#pragma unroll
    for (int i = 0; i < 16; i++) {
        v[i] = __expf(v[i] - mrow);
        s += v[i];
    }
#pragma unroll
    for (int o = 16; o > 0; o >>= 1)
        s += __shfl_xor_sync(0xFFFFFFFFu, s, o);
    if ((tid & 31) == 0) reds[tid >> 5] = s;
    __syncthreads();
    float tot = 0.0f;
#pragma unroll
    for (int w = 0; w < 8; w++) tot += reds[w];
    const float inv = 1.0f / tot;

#pragma unroll
    for (int i = 0; i < 16; i++)
        p[tid + i * 256] = round_tf32(v[i] * inv);
}

// ---------------------------------------------------------------------------
extern "C" void kernel_launch(void* const* d_in, const int* in_sizes, int n_in,
                              void* d_out, int out_size)
{
    const float* x = (const float*)d_in[0];   // [4, 4096, 768]
    const float* W = (const float*)d_in[1];   // [768, 2304]
    const float* b = (const float*)d_in[2];   // [2304]
    float* out = (float*)d_out;               // [4, 4096, 768]

    float *xr, *qkv, *S, *Wt, *Vt;
    cudaGetSymbolAddress((void**)&xr, g_x);
    cudaGetSymbolAddress((void**)&qkv, g_qkv);
    cudaGetSymbolAddress((void**)&S, g_S);
    cudaGetSymbolAddress((void**)&Wt, g_Wt);
    cudaGetSymbolAddress((void**)&Vt, g_Vt);

    cudaFuncSetAttribute(tc_gemm_nt<true, true>,   cudaFuncAttributeMaxDynamicSharedMemorySize, GEMM_DYNSMEM);
    cudaFuncSetAttribute(tc_gemm_nt<false, false>, cudaFuncAttributeMaxDynamicSharedMemorySize, GEMM_DYNSMEM);

    const size_t qkvStride = (size_t)NSEQ * H3;
    const size_t sStride   = (size_t)NSEQ * NSEQ;
    const size_t oStride   = (size_t)NSEQ * DIMC;
    const size_t vtStride  = (size_t)DIMC * NSEQ;

    // 0a) xr = tf32(x)
    round_copy_kernel<<<2048, 256>>>(x, xr, (size_t)BATCH * NSEQ * DIMC / 4);

    // 0b) Wt = tf32(W^T) : [768,2304] -> [2304,768]
    {
        dim3 grid(H3 / 32, DIMC / 32, 1);
        transpose_kernel<true><<<grid, dim3(32, 8)>>>(W, Wt, H3, DIMC, 0, 0);
    }

    // 1) qkv = tf32(xr @ Wt^T + b) : M=16384, N=2304, K=768
    {
        dim3 grid(H3 / 128, (BATCH * NSEQ) / 128, 1);
        tc_gemm_nt<true, true><<<grid, 256, GEMM_DYNSMEM>>>(
            xr, Wt, b, qkv, DIMC, DIMC, DIMC, H3, 0, 0, 0, 1.0f);
    }

    // 2) Vt = V^T per batch (values already tf32): [4096,768] -> [768,4096]
    {
        dim3 grid(DIMC / 32, NSEQ / 32, BATCH);
        transpose_kernel<false><<<grid, dim3(32, 8)>>>(qkv + 2 * DIMC, Vt, H3, NSEQ,
                                                       qkvStride, vtStride);
    }

    // 3) S = Q @ K^T * (1/sqrt(768)) per batch : M=N=4096, K=768
    {
        dim3 grid(NSEQ / 128, NSEQ / 128, BATCH);
        const float alpha = 1.0f / sqrtf((float)DIMC);
        tc_gemm_nt<false, false><<<grid, 256, GEMM_DYNSMEM>>>(
            qkv, qkv + DIMC, nullptr, S, DIMC, H3, H3, NSEQ,
            qkvStride, qkvStride, sStride, alpha);
    }

    // 4) softmax rows of S (emits tf32-rounded P)
    softmax_kernel<<<BATCH * NSEQ, 256>>>(S);

    // 5) out = P @ Vt^T per batch : M=4096, N=768, K=4096
    {
        dim3 grid(DIMC / 128, NSEQ / 128, BATCH);
        tc_gemm_nt<false, false><<<grid, 256, GEMM_DYNSMEM>>>(
            S, Vt, nullptr, out, NSEQ, NSEQ, NSEQ, DIMC,
            sStride, vtStride, oStride, 1.0f);
    }
}

// round 4
// speedup vs baseline: 3.5103x; 1.1362x over previous
#include <cuda_runtime.h>
#include <math.h>
#include <stdint.h>

// ---------------------------------------------------------------------------
// Problem constants
// ---------------------------------------------------------------------------
static constexpr int BATCH = 4;
static constexpr int NSEQ  = 4096;
static constexpr int DIMC  = 768;       // input dim == head dim
static constexpr int H3    = 3 * DIMC;  // 2304

// Scratch
__device__ float g_x[(size_t)BATCH * NSEQ * DIMC];            // ~50 MB (tf32-rounded x)
__device__ float g_qkv[(size_t)BATCH * NSEQ * H3];            // ~151 MB
__device__ float g_S[(size_t)BATCH * NSEQ * NSEQ];            // ~268 MB
__device__ float g_Wt[(size_t)H3 * DIMC];                     // ~7 MB  (W^T, tf32-rounded)
__device__ float g_Vt[(size_t)BATCH * DIMC * NSEQ];           // ~50 MB (V^T per batch)

// ---------------------------------------------------------------------------
// Helpers
// ---------------------------------------------------------------------------
__device__ __forceinline__ float round_tf32(float x) {
    uint32_t u;
    asm("cvt.rna.tf32.f32 %0, %1;" : "=r"(u) : "f"(x));
    return __uint_as_float(u);
}

__device__ __forceinline__ uint32_t smem_to_u32(const void* p) {
    uint32_t a;
    asm("{ .reg .u64 t; cvta.to.shared.u64 t, %1; cvt.u32.u64 %0, t; }"
        : "=r"(a) : "l"(p));
    return a;
}

__device__ __forceinline__ void cp_async16(uint32_t smem_addr, const void* gptr) {
    asm volatile("cp.async.cg.shared.global [%0], [%1], 16;"
                 :: "r"(smem_addr), "l"(gptr));
}

__device__ __forceinline__ void mma_tf32(float* d, const uint32_t* a, const uint32_t* b) {
    asm volatile(
        "mma.sync.aligned.m16n8k8.row.col.f32.tf32.tf32.f32 "
        "{%0,%1,%2,%3}, {%4,%5,%6,%7}, {%8,%9}, {%0,%1,%2,%3};"
        : "+f"(d[0]), "+f"(d[1]), "+f"(d[2]), "+f"(d[3])
        : "r"(a[0]), "r"(a[1]), "r"(a[2]), "r"(a[3]), "r"(b[0]), "r"(b[1]));
}

// ---------------------------------------------------------------------------
// tf32 mma.sync NT GEMM: C[M,N] = alpha * A[M,K] @ B[N,K]^T (+ bias[N])
// A, B K-major. Block tile 128x256x32, 256 threads (8 warps, warp tile 64x64,
// warps 2x4), 4-stage cp.async pipeline. Smem row stride 36 (conflict-free).
// Grid: (N/256, M/128, batch). Operands must be tf32-representable already.
// ---------------------------------------------------------------------------
static constexpr int STAGES = 4;
static constexpr int SROW = 36;                         // floats per smem row
static constexpr int A_STAGE_FLOATS = 128 * SROW;       // 4608
static constexpr int B_STAGE_FLOATS = 256 * SROW;       // 9216
static constexpr int A_STAGE_BYTES = A_STAGE_FLOATS * 4;
static constexpr int B_STAGE_BYTES = B_STAGE_FLOATS * 4;
static constexpr uint32_t GEMM_DYNSMEM =
    STAGES * (uint32_t)(A_STAGE_BYTES + B_STAGE_BYTES);  // 221184

template <bool BIAS, bool ROUND>
__global__ __launch_bounds__(256, 1)
void tc_gemm_nt(const float* __restrict__ A, const float* __restrict__ B,
                const float* __restrict__ bias, float* __restrict__ C,
                int K, int lda, int ldb, int ldc,
                size_t sA, size_t sB, size_t sC, float alpha)
{
    extern __shared__ float smem[];   // [STAGES][128][36] A, then [STAGES][256][36] B

    const int tid = threadIdx.x;
    const int lane = tid & 31;
    const int wid = tid >> 5;
    const int warp_m = wid & 1;       // 0..1  (64-row slab)
    const int warp_n = wid >> 1;      // 0..3  (64-col slab)
    const int bm = blockIdx.y * 128;
    const int bn = blockIdx.x * 256;

    const float* Abase = A + blockIdx.z * sA + (size_t)bm * lda;
    const float* Bbase = B + blockIdx.z * sB + (size_t)bn * ldb;
    C += blockIdx.z * sC;

    const uint32_t smemA_u = smem_to_u32(smem);
    const uint32_t smemB_u = smemA_u + STAGES * A_STAGE_BYTES;

    const int niter = K >> 5;

    // Producer: 1024 A-chunks + 2048 B-chunks of 16B per stage, 12 per thread
    auto issue = [&](int it) {
        if (it < niter) {
            const int s = it & (STAGES - 1);
            const uint32_t dA = smemA_u + s * A_STAGE_BYTES;
            const uint32_t dB = smemB_u + s * B_STAGE_BYTES;
            const int kofs = it * 32;
#pragma unroll
            for (int p = 0; p < 4; p++) {
                const int c = tid + 256 * p;
                const int r = c >> 3;
                const int col = (c & 7) * 4;
                cp_async16(dA + (uint32_t)(r * SROW + col) * 4u,
                           Abase + (size_t)r * lda + kofs + col);
            }
#pragma unroll
            for (int p = 0; p < 8; p++) {
                const int c = tid + 256 * p;
                const int r = c >> 3;
                const int col = (c & 7) * 4;
                cp_async16(dB + (uint32_t)(r * SROW + col) * 4u,
                           Bbase + (size_t)r * ldb + kofs + col);
            }
        }
        asm volatile("cp.async.commit_group;" ::: "memory");
    };

    issue(0); issue(1); issue(2);

    float acc[4][8][4];
#pragma unroll
    for (int mi = 0; mi < 4; mi++)
#pragma unroll
        for (int ni = 0; ni < 8; ni++)
#pragma unroll
            for (int j = 0; j < 4; j++) acc[mi][ni][j] = 0.0f;

    const int mrow = warp_m * 64 + (lane >> 2);
    const int nrow = warp_n * 64 + (lane >> 2);
    const int kc_base = lane & 3;

    for (int it = 0; it < niter; ++it) {
        asm volatile("cp.async.wait_group 2;" ::: "memory");
        __syncthreads();
        issue(it + 3);

        const int s = it & (STAGES - 1);
        const float* As_s = smem + s * A_STAGE_FLOATS;
        const float* Bs_s = smem + STAGES * A_STAGE_FLOATS + s * B_STAGE_FLOATS;

#pragma unroll
        for (int ks = 0; ks < 4; ks++) {
            const int kc = ks * 8 + kc_base;
            uint32_t afr[4][4];
            uint32_t bfr[8][2];
#pragma unroll
            for (int mi = 0; mi < 4; mi++) {
                const int r = mrow + mi * 16;
                afr[mi][0] = __float_as_uint(As_s[r * SROW + kc]);
                afr[mi][1] = __float_as_uint(As_s[(r + 8) * SROW + kc]);
                afr[mi][2] = __float_as_uint(As_s[r * SROW + kc + 4]);
                afr[mi][3] = __float_as_uint(As_s[(r + 8) * SROW + kc + 4]);
            }
#pragma unroll
            for (int ni = 0; ni < 8; ni++) {
                const int rn = nrow + ni * 8;
                bfr[ni][0] = __float_as_uint(Bs_s[rn * SROW + kc]);
                bfr[ni][1] = __float_as_uint(Bs_s[rn * SROW + kc + 4]);
            }
#pragma unroll
            for (int mi = 0; mi < 4; mi++)
#pragma unroll
                for (int ni = 0; ni < 8; ni++)
                    mma_tf32(acc[mi][ni], afr[mi], bfr[ni]);
        }
    }

    // Epilogue
    const int erow = bm + warp_m * 64 + (lane >> 2);
    const int ecol = bn + warp_n * 64 + (lane & 3) * 2;
#pragma unroll
    for (int mi = 0; mi < 4; mi++) {
#pragma unroll
        for (int ni = 0; ni < 8; ni++) {
            const int m0 = erow + mi * 16;
            const int n0 = ecol + ni * 8;
            float v0 = acc[mi][ni][0] * alpha;
            float v1 = acc[mi][ni][1] * alpha;
            float v2 = acc[mi][ni][2] * alpha;
            float v3 = acc[mi][ni][3] * alpha;
            if (BIAS) {
                const float b0 = bias[n0], b1 = bias[n0 + 1];
                v0 += b0; v1 += b1; v2 += b0; v3 += b1;
            }
            if (ROUND) {
                v0 = round_tf32(v0); v1 = round_tf32(v1);
                v2 = round_tf32(v2); v3 = round_tf32(v3);
            }
            *(float2*)(C + (size_t)m0 * ldc + n0)       = make_float2(v0, v1);
            *(float2*)(C + (size_t)(m0 + 8) * ldc + n0) = make_float2(v2, v3);
        }
    }
}

// ---------------------------------------------------------------------------
// Round-to-tf32 copy: dst[i] = tf32(src[i])
// ---------------------------------------------------------------------------
__global__ __launch_bounds__(256)
void round_copy_kernel(const float* __restrict__ src, float* __restrict__ dst, size_t n4)
{
    const size_t stride = (size_t)gridDim.x * 256;
    for (size_t i = blockIdx.x * 256ull + threadIdx.x; i < n4; i += stride) {
        float4 v = ((const float4*)src)[i];
        v.x = round_tf32(v.x); v.y = round_tf32(v.y);
        v.z = round_tf32(v.z); v.w = round_tf32(v.w);
        ((float4*)dst)[i] = v;
    }
}

// ---------------------------------------------------------------------------
// Tiled transpose: out[c, r] = op(in[r, c]); optional tf32 rounding.
// ---------------------------------------------------------------------------
template <bool ROUND>
__global__ __launch_bounds__(256)
void transpose_kernel(const float* __restrict__ in, float* __restrict__ out,
                      int ld_in, int ld_out, size_t sIn, size_t sOut)
{
    __shared__ float tile[32][33];
    in  += blockIdx.z * sIn;
    out += blockIdx.z * sOut;
    const int r0 = blockIdx.y * 32;
    const int c0 = blockIdx.x * 32;
    const int tx = threadIdx.x;
    const int ty = threadIdx.y;
#pragma unroll
    for (int i = 0; i < 32; i += 8) {
        float v = in[(size_t)(r0 + ty + i) * ld_in + c0 + tx];
        tile[ty + i][tx] = ROUND ? round_tf32(v) : v;
    }
    __syncthreads();
#pragma unroll
    for (int i = 0; i < 32; i += 8)
        out[(size_t)(c0 + ty + i) * ld_out + r0 + tx] = tile[tx][ty + i];
}

// ---------------------------------------------------------------------------
// Row softmax over g_S (rows = BATCH*NSEQ, cols = NSEQ); output tf32-rounded.
// ---------------------------------------------------------------------------
__global__ __launch_bounds__(256)
void softmax_kernel(float* __restrict__ S)
{
    const size_t row = blockIdx.x;
    float* p = S + row * (size_t)NSEQ;
    const int tid = threadIdx.x;

    float v[16];
    float m = -INFINITY;
#pragma unroll
    for (int i = 0; i < 16; i++) {
        v[i] = p[tid + i * 256];
        m = fmaxf(m, v[i]);
    }
#pragma unroll
    for (int o = 16; o > 0; o >>= 1)
        m = fmaxf(m, __shfl_xor_sync(0xFFFFFFFFu, m, o));

    __shared__ float redm[8];
    __shared__ float reds[8];
    if ((tid & 31) == 0) redm[tid >> 5] = m;
    __syncthreads();
    float mrow = redm[0];
#pragma unroll
    for (int w = 1; w < 8; w++) mrow = fmaxf(mrow, redm[w]);

    float s = 0.0f;
#pragma unroll
    for (int i = 0; i < 16; i++) {
        v[i] = __expf(v[i] - mrow);
        s += v[i];
    }
#pragma unroll
    for (int o = 16; o > 0; o >>= 1)
        s += __shfl_xor_sync(0xFFFFFFFFu, s, o);
    if ((tid & 31) == 0) reds[tid >> 5] = s;
    __syncthreads();
    float tot = 0.0f;
#pragma unroll
    for (int w = 0; w < 8; w++) tot += reds[w];
    const float inv = 1.0f / tot;

#pragma unroll
    for (int i = 0; i < 16; i++)
        p[tid + i * 256] = round_tf32(v[i] * inv);
}

// ---------------------------------------------------------------------------
extern "C" void kernel_launch(void* const* d_in, const int* in_sizes, int n_in,
                              void* d_out, int out_size)
{
    const float* x = (const float*)d_in[0];   // [4, 4096, 768]
    const float* W = (const float*)d_in[1];   // [768, 2304]
    const float* b = (const float*)d_in[2];   // [2304]
    float* out = (float*)d_out;               // [4, 4096, 768]

    float *xr, *qkv, *S, *Wt, *Vt;
    cudaGetSymbolAddress((void**)&xr, g_x);
    cudaGetSymbolAddress((void**)&qkv, g_qkv);
    cudaGetSymbolAddress((void**)&S, g_S);
    cudaGetSymbolAddress((void**)&Wt, g_Wt);
    cudaGetSymbolAddress((void**)&Vt, g_Vt);

    cudaFuncSetAttribute(tc_gemm_nt<true, true>,   cudaFuncAttributeMaxDynamicSharedMemorySize, GEMM_DYNSMEM);
    cudaFuncSetAttribute(tc_gemm_nt<false, false>, cudaFuncAttributeMaxDynamicSharedMemorySize, GEMM_DYNSMEM);

    const size_t qkvStride = (size_t)NSEQ * H3;
    const size_t sStride   = (size_t)NSEQ * NSEQ;
    const size_t oStride   = (size_t)NSEQ * DIMC;
    const size_t vtStride  = (size_t)DIMC * NSEQ;

    // 0a) xr = tf32(x)
    round_copy_kernel<<<2048, 256>>>(x, xr, (size_t)BATCH * NSEQ * DIMC / 4);

    // 0b) Wt = tf32(W^T) : [768,2304] -> [2304,768]
    {
        dim3 grid(H3 / 32, DIMC / 32, 1);
        transpose_kernel<true><<<grid, dim3(32, 8)>>>(W, Wt, H3, DIMC, 0, 0);
    }

    // 1) qkv = tf32(xr @ Wt^T + b) : M=16384, N=2304, K=768
    {
        dim3 grid(H3 / 256, (BATCH * NSEQ) / 128, 1);
        tc_gemm_nt<true, true><<<grid, 256, GEMM_DYNSMEM>>>(
            xr, Wt, b, qkv, DIMC, DIMC, DIMC, H3, 0, 0, 0, 1.0f);
    }

    // 2) Vt = V^T per batch (values already tf32): [4096,768] -> [768,4096]
    {
        dim3 grid(DIMC / 32, NSEQ / 32, BATCH);
        transpose_kernel<false><<<grid, dim3(32, 8)>>>(qkv + 2 * DIMC, Vt, H3, NSEQ,
                                                       qkvStride, vtStride);
    }

    // 3) S = Q @ K^T * (1/sqrt(768)) per batch : M=N=4096, K=768
    {
        dim3 grid(NSEQ / 256, NSEQ / 128, BATCH);
        const float alpha = 1.0f / sqrtf((float)DIMC);
        tc_gemm_nt<false, false><<<grid, 256, GEMM_DYNSMEM>>>(
            qkv, qkv + DIMC, nullptr, S, DIMC, H3, H3, NSEQ,
            qkvStride, qkvStride, sStride, alpha);
    }

    // 4) softmax rows of S (emits tf32-rounded P)
    softmax_kernel<<<BATCH * NSEQ, 256>>>(S);

    // 5) out = P @ Vt^T per batch : M=4096, N=768, K=4096
    {
        dim3 grid(DIMC / 256, NSEQ / 128, BATCH);
        tc_gemm_nt<false, false><<<grid, 256, GEMM_DYNSMEM>>>(
            S, Vt, nullptr, out, NSEQ, NSEQ, NSEQ, DIMC,
            sStride, vtStride, oStride, 1.0f);
    }
}

// round 6
// speedup vs baseline: 5.7597x; 1.6408x over previous
#include <cuda_runtime.h>
#include <cuda_fp16.h>
#include <math.h>
#include <stdint.h>

// ---------------------------------------------------------------------------
// Problem constants
// ---------------------------------------------------------------------------
static constexpr int BATCH = 4;
static constexpr int NSEQ  = 4096;
static constexpr int DIMC  = 768;       // input dim == head dim
static constexpr int H3    = 3 * DIMC;  // 2304

// Scratch
__device__ __half g_xh[(size_t)BATCH * NSEQ * DIMC];          // 25 MB
__device__ __half g_qkvh[(size_t)BATCH * NSEQ * H3];          // 75 MB
__device__ float  g_S[(size_t)BATCH * NSEQ * NSEQ];           // 268 MB
__device__ __half g_P[(size_t)BATCH * NSEQ * NSEQ];           // 134 MB
__device__ __half g_Wth[(size_t)H3 * DIMC];                   // 3.5 MB
__device__ __half g_Vth[(size_t)BATCH * DIMC * NSEQ];         // 25 MB

// ---------------------------------------------------------------------------
// Helpers
// ---------------------------------------------------------------------------
__device__ __forceinline__ uint32_t smem_to_u32(const void* p) {
    uint32_t a;
    asm("{ .reg .u64 t; cvta.to.shared.u64 t, %1; cvt.u32.u64 %0, t; }"
        : "=r"(a) : "l"(p));
    return a;
}

__device__ __forceinline__ void cp_async16(uint32_t smem_addr, const void* gptr) {
    asm volatile("cp.async.cg.shared.global [%0], [%1], 16;"
                 :: "r"(smem_addr), "l"(gptr));
}

#define LDSM_X4(r, addr) \
    asm volatile("ldmatrix.sync.aligned.m8n8.x4.shared.b16 {%0,%1,%2,%3}, [%4];" \
                 : "=r"((r)[0]), "=r"((r)[1]), "=r"((r)[2]), "=r"((r)[3]) : "r"(addr))

__device__ __forceinline__ void mma_f16(float* d, const uint32_t* a, const uint32_t* b) {
    asm volatile(
        "mma.sync.aligned.m16n8k16.row.col.f32.f16.f16.f32 "
        "{%0,%1,%2,%3}, {%4,%5,%6,%7}, {%8,%9}, {%0,%1,%2,%3};"
        : "+f"(d[0]), "+f"(d[1]), "+f"(d[2]), "+f"(d[3])
        : "r"(a[0]), "r"(a[1]), "r"(a[2]), "r"(a[3]), "r"(b[0]), "r"(b[1]));
}

// ---------------------------------------------------------------------------
// fp16 mma.sync NT GEMM: C[M,N] = alpha * A[M,K] @ B[N,K]^T (+ bias[N])
// A, B fp16 K-major. Block tile 128x256x32, 256 threads (8 warps, 2x4,
// warp tile 64x64), 4-stage cp.async pipeline. Smem row 40 halfs (80B,
// conflict-free for cp.async and ldmatrix). fp32 accumulate.
// Grid: (N/256, M/128, batch).
// ---------------------------------------------------------------------------
static constexpr int STAGES = 4;
static constexpr int SROWH = 40;                         // halfs per smem row
static constexpr int A_STAGE_BYTES = 128 * SROWH * 2;    // 10240
static constexpr int B_STAGE_BYTES = 256 * SROWH * 2;    // 20480
static constexpr uint32_t GEMM_DYNSMEM =
    STAGES * (uint32_t)(A_STAGE_BYTES + B_STAGE_BYTES);  // 122880

template <bool BIAS, bool OUT_HALF>
__global__ __launch_bounds__(256, 1)
void hgemm_nt(const __half* __restrict__ A, const __half* __restrict__ B,
              const float* __restrict__ bias, void* __restrict__ Cout,
              int K, int lda, int ldb, int ldc,
              size_t sA, size_t sB, size_t sC, float alpha)
{
    extern __shared__ __half hsmem[];

    const int tid = threadIdx.x;
    const int lane = tid & 31;
    const int wid = tid >> 5;
    const int warp_m = wid & 1;       // 0..1  (64-row slab)
    const int warp_n = wid >> 1;      // 0..3  (64-col slab)
    const int bm = blockIdx.y * 128;
    const int bn = blockIdx.x * 256;

    const __half* Abase = A + blockIdx.z * sA + (size_t)bm * lda;
    const __half* Bbase = B + blockIdx.z * sB + (size_t)bn * ldb;

    const uint32_t smemA_u = smem_to_u32(hsmem);
    const uint32_t smemB_u = smemA_u + STAGES * A_STAGE_BYTES;

    const int niter = K >> 5;

    // Producer: per stage A = 512 16B-chunks (2/thread), B = 1024 (4/thread)
    auto issue = [&](int it) {
        if (it < niter) {
            const int s = it & (STAGES - 1);
            const uint32_t dA = smemA_u + s * A_STAGE_BYTES;
            const uint32_t dB = smemB_u + s * B_STAGE_BYTES;
            const int kofs = it * 32;
#pragma unroll
            for (int p = 0; p < 2; p++) {
                const int c = tid + 256 * p;
                const int r = c >> 2, sub = c & 3;
                cp_async16(dA + (uint32_t)(r * 80 + sub * 16),
                           Abase + (size_t)r * lda + kofs + sub * 8);
            }
#pragma unroll
            for (int p = 0; p < 4; p++) {
                const int c = tid + 256 * p;
                const int r = c >> 2, sub = c & 3;
                cp_async16(dB + (uint32_t)(r * 80 + sub * 16),
                           Bbase + (size_t)r * ldb + kofs + sub * 8);
            }
        }
        asm volatile("cp.async.commit_group;" ::: "memory");
    };

    issue(0); issue(1); issue(2);

    float acc[4][8][4];
#pragma unroll
    for (int mi = 0; mi < 4; mi++)
#pragma unroll
        for (int ni = 0; ni < 8; ni++)
#pragma unroll
            for (int j = 0; j < 4; j++) acc[mi][ni][j] = 0.0f;

    // ldmatrix per-lane base byte offsets (within a stage), k-step 0
    const int laneM = lane >> 3;      // matrix id 0..3
    const int laneR = lane & 7;
    uint32_t aoff[4], boff[4];
#pragma unroll
    for (int mi = 0; mi < 4; mi++) {
        const int row = warp_m * 64 + mi * 16 + (laneM & 1) * 8 + laneR;
        aoff[mi] = (uint32_t)(row * SROWH + (laneM >> 1) * 8) * 2u;
    }
#pragma unroll
    for (int pi = 0; pi < 4; pi++) {
        const int row = warp_n * 64 + pi * 16 + (laneM >> 1) * 8 + laneR;
        boff[pi] = (uint32_t)(row * SROWH + (laneM & 1) * 8) * 2u;
    }

    for (int it = 0; it < niter; ++it) {
        asm volatile("cp.async.wait_group 2;" ::: "memory");
        __syncthreads();
        issue(it + 3);

        const int s = it & (STAGES - 1);
        const uint32_t sAu = smemA_u + s * A_STAGE_BYTES;
        const uint32_t sBu = smemB_u + s * B_STAGE_BYTES;

#pragma unroll
        for (int ks = 0; ks < 2; ks++) {           // two k=16 steps per chunk
            uint32_t afr[4][4];
            uint32_t bfr[4][4];   // pair pi holds {b0,b1} of n-tile 2pi and 2pi+1
#pragma unroll
            for (int mi = 0; mi < 4; mi++) LDSM_X4(afr[mi], sAu + aoff[mi] + ks * 32);
#pragma unroll
            for (int pi = 0; pi < 4; pi++) LDSM_X4(bfr[pi], sBu + boff[pi] + ks * 32);
#pragma unroll
            for (int mi = 0; mi < 4; mi++)
#pragma unroll
                for (int ni = 0; ni < 8; ni++)
                    mma_f16(acc[mi][ni], afr[mi], &bfr[ni >> 1][(ni & 1) * 2]);
        }
    }

    // Epilogue
    const int erow = bm + warp_m * 64 + (lane >> 2);
    const int ecol = bn + warp_n * 64 + (lane & 3) * 2;
#pragma unroll
    for (int mi = 0; mi < 4; mi++) {
#pragma unroll
        for (int ni = 0; ni < 8; ni++) {
            const int m0 = erow + mi * 16;
            const int n0 = ecol + ni * 8;
            float v0 = acc[mi][ni][0] * alpha;
            float v1 = acc[mi][ni][1] * alpha;
            float v2 = acc[mi][ni][2] * alpha;
            float v3 = acc[mi][ni][3] * alpha;
            if (BIAS) {
                const float b0 = bias[n0], b1 = bias[n0 + 1];
                v0 += b0; v1 += b1; v2 += b0; v3 += b1;
            }
            if (OUT_HALF) {
                __half* C = (__half*)Cout + blockIdx.z * sC;
                *(__half2*)(C + (size_t)m0 * ldc + n0)       = __floats2half2_rn(v0, v1);
                *(__half2*)(C + (size_t)(m0 + 8) * ldc + n0) = __floats2half2_rn(v2, v3);
            } else {
                float* C = (float*)Cout + blockIdx.z * sC;
                *(float2*)(C + (size_t)m0 * ldc + n0)       = make_float2(v0, v1);
                *(float2*)(C + (size_t)(m0 + 8) * ldc + n0) = make_float2(v2, v3);
            }
        }
    }
}

// ---------------------------------------------------------------------------
// fp32 -> fp16 copy
// ---------------------------------------------------------------------------
__global__ __launch_bounds__(256)
void f2h_kernel(const float* __restrict__ src, __half* __restrict__ dst, size_t n4)
{
    const size_t stride = (size_t)gridDim.x * 256;
    for (size_t i = blockIdx.x * 256ull + threadIdx.x; i < n4; i += stride) {
        float4 v = ((const float4*)src)[i];
        ((__half2*)dst)[2 * i]     = __floats2half2_rn(v.x, v.y);
        ((__half2*)dst)[2 * i + 1] = __floats2half2_rn(v.z, v.w);
    }
}

// ---------------------------------------------------------------------------
// Tiled transpose with dtype conversion: out[c, r] = in[r, c]
// ---------------------------------------------------------------------------
template <typename TIN, typename TOUT>
__global__ __launch_bounds__(256)
void transpose_t(const TIN* __restrict__ in, TOUT* __restrict__ out,
                 int ld_in, int ld_out, size_t sIn, size_t sOut)
{
    __shared__ float tile[32][33];
    in  += blockIdx.z * sIn;
    out += blockIdx.z * sOut;
    const int r0 = blockIdx.y * 32;
    const int c0 = blockIdx.x * 32;
    const int tx = threadIdx.x;
    const int ty = threadIdx.y;
#pragma unroll
    for (int i = 0; i < 32; i += 8)
        tile[ty + i][tx] = (float)in[(size_t)(r0 + ty + i) * ld_in + c0 + tx];
    __syncthreads();
#pragma unroll
    for (int i = 0; i < 32; i += 8)
        out[(size_t)(c0 + ty + i) * ld_out + r0 + tx] = (TOUT)tile[tx][ty + i];
}

// ---------------------------------------------------------------------------
// Row softmax: reads fp32 S row, writes fp16 P row. rows = BATCH*NSEQ.
// ---------------------------------------------------------------------------
__global__ __launch_bounds__(256)
void softmax_kernel(const float* __restrict__ S, __half* __restrict__ P)
{
    const size_t row = blockIdx.x;
    const float2* p = (const float2*)(S + row * (size_t)NSEQ);
    __half2* q = (__half2*)(P + row * (size_t)NSEQ);
    const int tid = threadIdx.x;

    float2 v[8];
    float m = -INFINITY;
#pragma unroll
    for (int i = 0; i < 8; i++) {
        v[i] = p[tid + i * 256];
        m = fmaxf(m, fmaxf(v[i].x, v[i].y));
    }
#pragma unroll
    for (int o = 16; o > 0; o >>= 1)
        m = fmaxf(m, __shfl_xor_sync(0xFFFFFFFFu, m, o));

    __shared__ float redm[8];
    __shared__ float reds[8];
    if ((tid & 31) == 0) redm[tid >> 5] = m;
    __syncthreads();
    float mrow = redm[0];
#pragma unroll
    for (int w = 1; w < 8; w++) mrow = fmaxf(mrow, redm[w]);

    float s = 0.0f;
#pragma unroll
    for (int i = 0; i < 8; i++) {
        v[i].x = __expf(v[i].x - mrow);
        v[i].y = __expf(v[i].y - mrow);
        s += v[i].x + v[i].y;
    }
#pragma unroll
    for (int o = 16; o > 0; o >>= 1)
        s += __shfl_xor_sync(0xFFFFFFFFu, s, o);
    if ((tid & 31) == 0) reds[tid >> 5] = s;
    __syncthreads();
    float tot = 0.0f;
#pragma unroll
    for (int w = 0; w < 8; w++) tot += reds[w];
    const float inv = 1.0f / tot;

#pragma unroll
    for (int i = 0; i < 8; i++)
        q[tid + i * 256] = __floats2half2_rn(v[i].x * inv, v[i].y * inv);
}

// ---------------------------------------------------------------------------
extern "C" void kernel_launch(void* const* d_in, const int* in_sizes, int n_in,
                              void* d_out, int out_size)
{
    const float* x = (const float*)d_in[0];   // [4, 4096, 768]
    const float* W = (const float*)d_in[1];   // [768, 2304]
    const float* b = (const float*)d_in[2];   // [2304]
    float* out = (float*)d_out;               // [4, 4096, 768]

    __half *xh, *qkvh, *P, *Wth, *Vth;
    float *S;
    cudaGetSymbolAddress((void**)&xh, g_xh);
    cudaGetSymbolAddress((void**)&qkvh, g_qkvh);
    cudaGetSymbolAddress((void**)&S, g_S);
    cudaGetSymbolAddress((void**)&P, g_P);
    cudaGetSymbolAddress((void**)&Wth, g_Wth);
    cudaGetSymbolAddress((void**)&Vth, g_Vth);

    cudaFuncSetAttribute(hgemm_nt<true, true>,   cudaFuncAttributeMaxDynamicSharedMemorySize, GEMM_DYNSMEM);
    cudaFuncSetAttribute(hgemm_nt<false, false>, cudaFuncAttributeMaxDynamicSharedMemorySize, GEMM_DYNSMEM);

    const size_t qkvStride = (size_t)NSEQ * H3;
    const size_t sStride   = (size_t)NSEQ * NSEQ;
    const size_t oStride   = (size_t)NSEQ * DIMC;
    const size_t vtStride  = (size_t)DIMC * NSEQ;

    // 0a) xh = fp16(x)
    f2h_kernel<<<2048, 256>>>(x, xh, (size_t)BATCH * NSEQ * DIMC / 4);

    // 0b) Wth = fp16(W^T) : [768,2304] -> [2304,768]
    {
        dim3 grid(H3 / 32, DIMC / 32, 1);
        transpose_t<float, __half><<<grid, dim3(32, 8)>>>(W, Wth, H3, DIMC, 0, 0);
    }

    // 1) qkvh = fp16(xh @ Wth^T + b) : M=16384, N=2304, K=768
    {
        dim3 grid(H3 / 256, (BATCH * NSEQ) / 128, 1);
        hgemm_nt<true, true><<<grid, 256, GEMM_DYNSMEM>>>(
            xh, Wth, b, qkvh, DIMC, DIMC, DIMC, H3, 0, 0, 0, 1.0f);
    }

    // 2) Vth = V^T per batch : [4096,768] -> [768,4096]
    {
        dim3 grid(DIMC / 32, NSEQ / 32, BATCH);
        transpose_t<__half, __half><<<grid, dim3(32, 8)>>>(qkvh + 2 * DIMC, Vth, H3, NSEQ,
                                                           qkvStride, vtStride);
    }

    // 3) S = Q @ K^T * (1/sqrt(768)) per batch (fp32 out) : M=N=4096, K=768
    {
        dim3 grid(NSEQ / 256, NSEQ / 128, BATCH);
        const float alpha = 1.0f / sqrtf((float)DIMC);
        hgemm_nt<false, false><<<grid, 256, GEMM_DYNSMEM>>>(
            qkvh, qkvh + DIMC, nullptr, S, DIMC, H3, H3, NSEQ,
            qkvStride, qkvStride, sStride, alpha);
    }

    // 4) softmax rows of S -> fp16 P
    softmax_kernel<<<BATCH * NSEQ, 256>>>(S, P);

    // 5) out = P @ Vth^T per batch (fp32 out) : M=4096, N=768, K=4096
    {
        dim3 grid(DIMC / 256, NSEQ / 128, BATCH);
        hgemm_nt<false, false><<<grid, 256, GEMM_DYNSMEM>>>(
            P, Vth, nullptr, out, NSEQ, NSEQ, NSEQ, DIMC,
            sStride, vtStride, oStride, 1.0f);
    }
}

// round 7
// speedup vs baseline: 6.6709x; 1.1582x over previous
#include <cuda_runtime.h>
#include <cuda_fp16.h>
#include <math.h>
#include <stdint.h>

// ---------------------------------------------------------------------------
// Problem constants
// ---------------------------------------------------------------------------
static constexpr int BATCH = 4;
static constexpr int NSEQ  = 4096;
static constexpr int DIMC  = 768;       // input dim == head dim
static constexpr int H3    = 3 * DIMC;  // 2304

// Scratch
__device__ __half g_xh[(size_t)BATCH * NSEQ * DIMC];          // 25 MB
__device__ __half g_qkvh[(size_t)BATCH * NSEQ * H3];          // 75 MB
__device__ float  g_S[(size_t)BATCH * NSEQ * NSEQ];           // 268 MB
__device__ __half g_P[(size_t)BATCH * NSEQ * NSEQ];           // 134 MB
__device__ __half g_Wth[(size_t)H3 * DIMC];                   // 3.5 MB
__device__ __half g_Vth[(size_t)BATCH * DIMC * NSEQ];         // 25 MB

// ---------------------------------------------------------------------------
// Helpers
// ---------------------------------------------------------------------------
__device__ __forceinline__ uint32_t smem_to_u32(const void* p) {
    uint32_t a;
    asm("{ .reg .u64 t; cvta.to.shared.u64 t, %1; cvt.u32.u64 %0, t; }"
        : "=r"(a) : "l"(p));
    return a;
}

__device__ __forceinline__ void cp_async16(uint32_t smem_addr, const void* gptr) {
    asm volatile("cp.async.cg.shared.global [%0], [%1], 16;"
                 :: "r"(smem_addr), "l"(gptr));
}

#define LDSM_X4(r, addr) \
    asm volatile("ldmatrix.sync.aligned.m8n8.x4.shared.b16 {%0,%1,%2,%3}, [%4];" \
                 : "=r"((r)[0]), "=r"((r)[1]), "=r"((r)[2]), "=r"((r)[3]) : "r"(addr))

__device__ __forceinline__ void mma_f16(float* d, const uint32_t* a, const uint32_t* b) {
    asm volatile(
        "mma.sync.aligned.m16n8k16.row.col.f32.f16.f16.f32 "
        "{%0,%1,%2,%3}, {%4,%5,%6,%7}, {%8,%9}, {%0,%1,%2,%3};"
        : "+f"(d[0]), "+f"(d[1]), "+f"(d[2]), "+f"(d[3])
        : "r"(a[0]), "r"(a[1]), "r"(a[2]), "r"(a[3]), "r"(b[0]), "r"(b[1]));
}

// ---------------------------------------------------------------------------
// fp16 mma.sync NT GEMM: C[M,N] = alpha * A[M,K] @ B[N,K]^T (+ bias[N])
// A, B fp16 K-major. Block tile 128x128x32, 256 threads (8 warps as 2x4,
// warp tile 64x32), 4-stage cp.async pipeline, 2 CTAs/SM.
// Smem row 40 halfs (80B, conflict-free for cp.async and ldmatrix).
// fp32 accumulate. Grid: (N/128, M/128, batch).
// ---------------------------------------------------------------------------
static constexpr int STAGES = 4;
static constexpr int SROWH = 40;                         // halfs per smem row
static constexpr int T_STAGE_BYTES = 128 * SROWH * 2;    // 10240 (each of A and B)
static constexpr uint32_t GEMM_DYNSMEM =
    STAGES * 2u * (uint32_t)T_STAGE_BYTES;               // 81920

template <bool BIAS, bool OUT_HALF>
__global__ __launch_bounds__(256, 2)
void hgemm_nt(const __half* __restrict__ A, const __half* __restrict__ B,
              const float* __restrict__ bias, void* __restrict__ Cout,
              int K, int lda, int ldb, int ldc,
              size_t sA, size_t sB, size_t sC, float alpha)
{
    extern __shared__ __half hsmem[];

    const int tid = threadIdx.x;
    const int lane = tid & 31;
    const int wid = tid >> 5;
    const int warp_m = wid & 1;       // 0..1  (64-row slab)
    const int warp_n = wid >> 1;      // 0..3  (32-col slab)
    const int bm = blockIdx.y * 128;
    const int bn = blockIdx.x * 128;

    const __half* Abase = A + blockIdx.z * sA + (size_t)bm * lda;
    const __half* Bbase = B + blockIdx.z * sB + (size_t)bn * ldb;

    const uint32_t smemA_u = smem_to_u32(hsmem);
    const uint32_t smemB_u = smemA_u + STAGES * T_STAGE_BYTES;

    const int niter = K >> 5;

    // Producer: per stage A = 512 16B-chunks (2/thread), B = 512 (2/thread)
    auto issue = [&](int it) {
        if (it < niter) {
            const int s = it & (STAGES - 1);
            const uint32_t dA = smemA_u + s * T_STAGE_BYTES;
            const uint32_t dB = smemB_u + s * T_STAGE_BYTES;
            const int kofs = it * 32;
#pragma unroll
            for (int p = 0; p < 2; p++) {
                const int c = tid + 256 * p;
                const int r = c >> 2, sub = c & 3;
                cp_async16(dA + (uint32_t)(r * 80 + sub * 16),
                           Abase + (size_t)r * lda + kofs + sub * 8);
                cp_async16(dB + (uint32_t)(r * 80 + sub * 16),
                           Bbase + (size_t)r * ldb + kofs + sub * 8);
            }
        }
        asm volatile("cp.async.commit_group;" ::: "memory");
    };

    issue(0); issue(1); issue(2);

    float acc[4][4][4];
#pragma unroll
    for (int mi = 0; mi < 4; mi++)
#pragma unroll
        for (int ni = 0; ni < 4; ni++)
#pragma unroll
            for (int j = 0; j < 4; j++) acc[mi][ni][j] = 0.0f;

    // ldmatrix per-lane base byte offsets (within a stage), k-step 0
    const int laneM = lane >> 3;      // matrix id 0..3
    const int laneR = lane & 7;
    uint32_t aoff[4], boff[2];
#pragma unroll
    for (int mi = 0; mi < 4; mi++) {
        const int row = warp_m * 64 + mi * 16 + (laneM & 1) * 8 + laneR;
        aoff[mi] = (uint32_t)(row * SROWH + (laneM >> 1) * 8) * 2u;
    }
#pragma unroll
    for (int pi = 0; pi < 2; pi++) {
        const int row = warp_n * 32 + pi * 16 + (laneM >> 1) * 8 + laneR;
        boff[pi] = (uint32_t)(row * SROWH + (laneM & 1) * 8) * 2u;
    }

    for (int it = 0; it < niter; ++it) {
        asm volatile("cp.async.wait_group 2;" ::: "memory");
        __syncthreads();
        issue(it + 3);

        const int s = it & (STAGES - 1);
        const uint32_t sAu = smemA_u + s * T_STAGE_BYTES;
        const uint32_t sBu = smemB_u + s * T_STAGE_BYTES;

#pragma unroll
        for (int ks = 0; ks < 2; ks++) {           // two k=16 steps per chunk
            uint32_t afr[4][4];
            uint32_t bfr[2][4];   // pair pi holds frags of n-tiles 2pi, 2pi+1
#pragma unroll
            for (int mi = 0; mi < 4; mi++) LDSM_X4(afr[mi], sAu + aoff[mi] + ks * 32);
#pragma unroll
            for (int pi = 0; pi < 2; pi++) LDSM_X4(bfr[pi], sBu + boff[pi] + ks * 32);
#pragma unroll
            for (int mi = 0; mi < 4; mi++)
#pragma unroll
                for (int ni = 0; ni < 4; ni++)
                    mma_f16(acc[mi][ni], afr[mi], &bfr[ni >> 1][(ni & 1) * 2]);
        }
    }

    // Epilogue
    const int erow = bm + warp_m * 64 + (lane >> 2);
    const int ecol = bn + warp_n * 32 + (lane & 3) * 2;
#pragma unroll
    for (int mi = 0; mi < 4; mi++) {
#pragma unroll
        for (int ni = 0; ni < 4; ni++) {
            const int m0 = erow + mi * 16;
            const int n0 = ecol + ni * 8;
            float v0 = acc[mi][ni][0] * alpha;
            float v1 = acc[mi][ni][1] * alpha;
            float v2 = acc[mi][ni][2] * alpha;
            float v3 = acc[mi][ni][3] * alpha;
            if (BIAS) {
                const float b0 = bias[n0], b1 = bias[n0 + 1];
                v0 += b0; v1 += b1; v2 += b0; v3 += b1;
            }
            if (OUT_HALF) {
                __half* C = (__half*)Cout + blockIdx.z * sC;
                *(__half2*)(C + (size_t)m0 * ldc + n0)       = __floats2half2_rn(v0, v1);
                *(__half2*)(C + (size_t)(m0 + 8) * ldc + n0) = __floats2half2_rn(v2, v3);
            } else {
                float* C = (float*)Cout + blockIdx.z * sC;
                *(float2*)(C + (size_t)m0 * ldc + n0)       = make_float2(v0, v1);
                *(float2*)(C + (size_t)(m0 + 8) * ldc + n0) = make_float2(v2, v3);
            }
        }
    }
}

// ---------------------------------------------------------------------------
// fp32 -> fp16 copy
// ---------------------------------------------------------------------------
__global__ __launch_bounds__(256)
void f2h_kernel(const float* __restrict__ src, __half* __restrict__ dst, size_t n4)
{
    const size_t stride = (size_t)gridDim.x * 256;
    for (size_t i = blockIdx.x * 256ull + threadIdx.x; i < n4; i += stride) {
        float4 v = ((const float4*)src)[i];
        ((__half2*)dst)[2 * i]     = __floats2half2_rn(v.x, v.y);
        ((__half2*)dst)[2 * i + 1] = __floats2half2_rn(v.z, v.w);
    }
}

// ---------------------------------------------------------------------------
// Tiled transpose with dtype conversion: out[c, r] = in[r, c]
// ---------------------------------------------------------------------------
template <typename TIN, typename TOUT>
__global__ __launch_bounds__(256)
void transpose_t(const TIN* __restrict__ in, TOUT* __restrict__ out,
                 int ld_in, int ld_out, size_t sIn, size_t sOut)
{
    __shared__ float tile[32][33];
    in  += blockIdx.z * sIn;
    out += blockIdx.z * sOut;
    const int r0 = blockIdx.y * 32;
    const int c0 = blockIdx.x * 32;
    const int tx = threadIdx.x;
    const int ty = threadIdx.y;
#pragma unroll
    for (int i = 0; i < 32; i += 8)
        tile[ty + i][tx] = (float)in[(size_t)(r0 + ty + i) * ld_in + c0 + tx];
    __syncthreads();
#pragma unroll
    for (int i = 0; i < 32; i += 8)
        out[(size_t)(c0 + ty + i) * ld_out + r0 + tx] = (TOUT)tile[tx][ty + i];
}

// ---------------------------------------------------------------------------
// Row softmax: reads fp32 S row, writes fp16 P row. rows = BATCH*NSEQ.
// ---------------------------------------------------------------------------
__global__ __launch_bounds__(256)
void softmax_kernel(const float* __restrict__ S, __half* __restrict__ P)
{
    const size_t row = blockIdx.x;
    const float2* p = (const float2*)(S + row * (size_t)NSEQ);
    __half2* q = (__half2*)(P + row * (size_t)NSEQ);
    const int tid = threadIdx.x;

    float2 v[8];
    float m = -INFINITY;
#pragma unroll
    for (int i = 0; i < 8; i++) {
        v[i] = p[tid + i * 256];
        m = fmaxf(m, fmaxf(v[i].x, v[i].y));
    }
#pragma unroll
    for (int o = 16; o > 0; o >>= 1)
        m = fmaxf(m, __shfl_xor_sync(0xFFFFFFFFu, m, o));

    __shared__ float redm[8];
    __shared__ float reds[8];
    if ((tid & 31) == 0) redm[tid >> 5] = m;
    __syncthreads();
    float mrow = redm[0];
#pragma unroll
    for (int w = 1; w < 8; w++) mrow = fmaxf(mrow, redm[w]);

    float s = 0.0f;
#pragma unroll
    for (int i = 0; i < 8; i++) {
        v[i].x = __expf(v[i].x - mrow);
        v[i].y = __expf(v[i].y - mrow);
        s += v[i].x + v[i].y;
    }
#pragma unroll
    for (int o = 16; o > 0; o >>= 1)
        s += __shfl_xor_sync(0xFFFFFFFFu, s, o);
    if ((tid & 31) == 0) reds[tid >> 5] = s;
    __syncthreads();
    float tot = 0.0f;
#pragma unroll
    for (int w = 0; w < 8; w++) tot += reds[w];
    const float inv = 1.0f / tot;

#pragma unroll
    for (int i = 0; i < 8; i++)
        q[tid + i * 256] = __floats2half2_rn(v[i].x * inv, v[i].y * inv);
}

// ---------------------------------------------------------------------------
extern "C" void kernel_launch(void* const* d_in, const int* in_sizes, int n_in,
                              void* d_out, int out_size)
{
    const float* x = (const float*)d_in[0];   // [4, 4096, 768]
    const float* W = (const float*)d_in[1];   // [768, 2304]
    const float* b = (const float*)d_in[2];   // [2304]
    float* out = (float*)d_out;               // [4, 4096, 768]

    __half *xh, *qkvh, *P, *Wth, *Vth;
    float *S;
    cudaGetSymbolAddress((void**)&xh, g_xh);
    cudaGetSymbolAddress((void**)&qkvh, g_qkvh);
    cudaGetSymbolAddress((void**)&S, g_S);
    cudaGetSymbolAddress((void**)&P, g_P);
    cudaGetSymbolAddress((void**)&Wth, g_Wth);
    cudaGetSymbolAddress((void**)&Vth, g_Vth);

    cudaFuncSetAttribute(hgemm_nt<true, true>,   cudaFuncAttributeMaxDynamicSharedMemorySize, GEMM_DYNSMEM);
    cudaFuncSetAttribute(hgemm_nt<false, false>, cudaFuncAttributeMaxDynamicSharedMemorySize, GEMM_DYNSMEM);

    const size_t qkvStride = (size_t)NSEQ * H3;
    const size_t sStride   = (size_t)NSEQ * NSEQ;
    const size_t oStride   = (size_t)NSEQ * DIMC;
    const size_t vtStride  = (size_t)DIMC * NSEQ;

    // 0a) xh = fp16(x)
    f2h_kernel<<<2048, 256>>>(x, xh, (size_t)BATCH * NSEQ * DIMC / 4);

    // 0b) Wth = fp16(W^T) : [768,2304] -> [2304,768]
    {
        dim3 grid(H3 / 32, DIMC / 32, 1);
        transpose_t<float, __half><<<grid, dim3(32, 8)>>>(W, Wth, H3, DIMC, 0, 0);
    }

    // 1) qkvh = fp16(xh @ Wth^T + b) : M=16384, N=2304, K=768
    {
        dim3 grid(H3 / 128, (BATCH * NSEQ) / 128, 1);
        hgemm_nt<true, true><<<grid, 256, GEMM_DYNSMEM>>>(
            xh, Wth, b, qkvh, DIMC, DIMC, DIMC, H3, 0, 0, 0, 1.0f);
    }

    // 2) Vth = V^T per batch : [4096,768] -> [768,4096]
    {
        dim3 grid(DIMC / 32, NSEQ / 32, BATCH);
        transpose_t<__half, __half><<<grid, dim3(32, 8)>>>(qkvh + 2 * DIMC, Vth, H3, NSEQ,
                                                           qkvStride, vtStride);
    }

    // 3) S = Q @ K^T * (1/sqrt(768)) per batch (fp32 out) : M=N=4096, K=768
    {
        dim3 grid(NSEQ / 128, NSEQ / 128, BATCH);
        const float alpha = 1.0f / sqrtf((float)DIMC);
        hgemm_nt<false, false><<<grid, 256, GEMM_DYNSMEM>>>(
            qkvh, qkvh + DIMC, nullptr, S, DIMC, H3, H3, NSEQ,
            qkvStride, qkvStride, sStride, alpha);
    }

    // 4) softmax rows of S -> fp16 P
    softmax_kernel<<<BATCH * NSEQ, 256>>>(S, P);

    // 5) out = P @ Vth^T per batch (fp32 out) : M=4096, N=768, K=4096
    {
        dim3 grid(DIMC / 128, NSEQ / 128, BATCH);
        hgemm_nt<false, false><<<grid, 256, GEMM_DYNSMEM>>>(
            P, Vth, nullptr, out, NSEQ, NSEQ, NSEQ, DIMC,
            sStride, vtStride, oStride, 1.0f);
    }
}

// round 8
// speedup vs baseline: 6.7752x; 1.0156x over previous
#include <cuda_runtime.h>
#include <cuda_fp16.h>
#include <math.h>
#include <stdint.h>

// ---------------------------------------------------------------------------
// Problem constants
// ---------------------------------------------------------------------------
static constexpr int BATCH = 4;
static constexpr int NSEQ  = 4096;
static constexpr int DIMC  = 768;       // input dim == head dim
static constexpr int H3    = 3 * DIMC;  // 2304

// Scratch
__device__ __half g_xh[(size_t)BATCH * NSEQ * DIMC];          // 25 MB
__device__ __half g_qkvh[(size_t)BATCH * NSEQ * H3];          // 75 MB
__device__ float  g_S[(size_t)BATCH * NSEQ * NSEQ];           // 268 MB
__device__ __half g_P[(size_t)BATCH * NSEQ * NSEQ];           // 134 MB
__device__ __half g_Wth[(size_t)H3 * DIMC];                   // 3.5 MB
__device__ __half g_Vth[(size_t)BATCH * DIMC * NSEQ];         // 25 MB

// ---------------------------------------------------------------------------
// Helpers
// ---------------------------------------------------------------------------
__device__ __forceinline__ uint32_t smem_to_u32(const void* p) {
    uint32_t a;
    asm("{ .reg .u64 t; cvta.to.shared.u64 t, %1; cvt.u32.u64 %0, t; }"
        : "=r"(a) : "l"(p));
    return a;
}

__device__ __forceinline__ void cp_async16(uint32_t smem_addr, const void* gptr) {
    asm volatile("cp.async.cg.shared.global [%0], [%1], 16;"
                 :: "r"(smem_addr), "l"(gptr));
}

#define LDSM_X4(r, addr) \
    asm volatile("ldmatrix.sync.aligned.m8n8.x4.shared.b16 {%0,%1,%2,%3}, [%4];" \
                 : "=r"((r)[0]), "=r"((r)[1]), "=r"((r)[2]), "=r"((r)[3]) : "r"(addr))

__device__ __forceinline__ void mma_f16(float* d, const uint32_t* a, const uint32_t* b) {
    asm volatile(
        "mma.sync.aligned.m16n8k16.row.col.f32.f16.f16.f32 "
        "{%0,%1,%2,%3}, {%4,%5,%6,%7}, {%8,%9}, {%0,%1,%2,%3};"
        : "+f"(d[0]), "+f"(d[1]), "+f"(d[2]), "+f"(d[3])
        : "r"(a[0]), "r"(a[1]), "r"(a[2]), "r"(a[3]), "r"(b[0]), "r"(b[1]));
}

// ---------------------------------------------------------------------------
// fp16 mma.sync NT GEMM: C[M,N] = alpha * A[M,K] @ B[N,K]^T (+ bias[N])
// A, B fp16 K-major. Block tile 128x128x32, 128 threads (4 warps as 2x2,
// warp tile 64x64), 3-stage cp.async pipeline, 3 CTAs/SM.
// Smem row 40 halfs (80B, conflict-free for cp.async and ldmatrix).
// fp32 accumulate. Grid: (N/128, M/128, batch).
// ---------------------------------------------------------------------------
static constexpr int STAGES = 3;
static constexpr int SROWH = 40;                         // halfs per smem row
static constexpr int T_STAGE_BYTES = 128 * SROWH * 2;    // 10240 (each of A and B)
static constexpr uint32_t GEMM_DYNSMEM =
    STAGES * 2u * (uint32_t)T_STAGE_BYTES;               // 61440

template <bool BIAS, bool OUT_HALF>
__global__ __launch_bounds__(128, 3)
void hgemm_nt(const __half* __restrict__ A, const __half* __restrict__ B,
              const float* __restrict__ bias, void* __restrict__ Cout,
              int K, int lda, int ldb, int ldc,
              size_t sA, size_t sB, size_t sC, float alpha)
{
    extern __shared__ __half hsmem[];

    const int tid = threadIdx.x;
    const int lane = tid & 31;
    const int wid = tid >> 5;
    const int warp_m = wid & 1;       // 0..1  (64-row slab)
    const int warp_n = wid >> 1;      // 0..1  (64-col slab)
    const int bm = blockIdx.y * 128;
    const int bn = blockIdx.x * 128;

    const __half* Abase = A + blockIdx.z * sA + (size_t)bm * lda;
    const __half* Bbase = B + blockIdx.z * sB + (size_t)bn * ldb;

    const uint32_t smemA_u = smem_to_u32(hsmem);
    const uint32_t smemB_u = smemA_u + STAGES * T_STAGE_BYTES;

    const int niter = K >> 5;

    // Producer: per stage A = 512 16B-chunks (4/thread), B = 512 (4/thread)
    auto issue = [&](int it) {
        if (it < niter) {
            const int s = it % STAGES;
            const uint32_t dA = smemA_u + s * T_STAGE_BYTES;
            const uint32_t dB = smemB_u + s * T_STAGE_BYTES;
            const int kofs = it * 32;
#pragma unroll
            for (int p = 0; p < 4; p++) {
                const int c = tid + 128 * p;
                const int r = c >> 2, sub = c & 3;
                cp_async16(dA + (uint32_t)(r * 80 + sub * 16),
                           Abase + (size_t)r * lda + kofs + sub * 8);
                cp_async16(dB + (uint32_t)(r * 80 + sub * 16),
                           Bbase + (size_t)r * ldb + kofs + sub * 8);
            }
        }
        asm volatile("cp.async.commit_group;" ::: "memory");
    };

    issue(0); issue(1);

    float acc[4][8][4];
#pragma unroll
    for (int mi = 0; mi < 4; mi++)
#pragma unroll
        for (int ni = 0; ni < 8; ni++)
#pragma unroll
            for (int j = 0; j < 4; j++) acc[mi][ni][j] = 0.0f;

    // ldmatrix per-lane base byte offsets (within a stage), k-step 0
    const int laneM = lane >> 3;      // matrix id 0..3
    const int laneR = lane & 7;
    uint32_t aoff[4], boff[4];
#pragma unroll
    for (int mi = 0; mi < 4; mi++) {
        const int row = warp_m * 64 + mi * 16 + (laneM & 1) * 8 + laneR;
        aoff[mi] = (uint32_t)(row * SROWH + (laneM >> 1) * 8) * 2u;
    }
#pragma unroll
    for (int pi = 0; pi < 4; pi++) {
        const int row = warp_n * 64 + pi * 16 + (laneM >> 1) * 8 + laneR;
        boff[pi] = (uint32_t)(row * SROWH + (laneM & 1) * 8) * 2u;
    }

    for (int it = 0; it < niter; ++it) {
        asm volatile("cp.async.wait_group 1;" ::: "memory");
        __syncthreads();
        issue(it + 2);

        const int s = it % STAGES;
        const uint32_t sAu = smemA_u + s * T_STAGE_BYTES;
        const uint32_t sBu = smemB_u + s * T_STAGE_BYTES;

#pragma unroll
        for (int ks = 0; ks < 2; ks++) {           // two k=16 steps per chunk
            uint32_t afr[4][4];
            uint32_t bfr[4][4];   // pair pi holds frags of n-tiles 2pi, 2pi+1
#pragma unroll
            for (int mi = 0; mi < 4; mi++) LDSM_X4(afr[mi], sAu + aoff[mi] + ks * 32);
#pragma unroll
            for (int pi = 0; pi < 4; pi++) LDSM_X4(bfr[pi], sBu + boff[pi] + ks * 32);
#pragma unroll
            for (int mi = 0; mi < 4; mi++)
#pragma unroll
                for (int ni = 0; ni < 8; ni++)
                    mma_f16(acc[mi][ni], afr[mi], &bfr[ni >> 1][(ni & 1) * 2]);
        }
    }

    // Epilogue
    const int erow = bm + warp_m * 64 + (lane >> 2);
    const int ecol = bn + warp_n * 64 + (lane & 3) * 2;
#pragma unroll
    for (int mi = 0; mi < 4; mi++) {
#pragma unroll
        for (int ni = 0; ni < 8; ni++) {
            const int m0 = erow + mi * 16;
            const int n0 = ecol + ni * 8;
            float v0 = acc[mi][ni][0] * alpha;
            float v1 = acc[mi][ni][1] * alpha;
            float v2 = acc[mi][ni][2] * alpha;
            float v3 = acc[mi][ni][3] * alpha;
            if (BIAS) {
                const float b0 = bias[n0], b1 = bias[n0 + 1];
                v0 += b0; v1 += b1; v2 += b0; v3 += b1;
            }
            if (OUT_HALF) {
                __half* C = (__half*)Cout + blockIdx.z * sC;
                *(__half2*)(C + (size_t)m0 * ldc + n0)       = __floats2half2_rn(v0, v1);
                *(__half2*)(C + (size_t)(m0 + 8) * ldc + n0) = __floats2half2_rn(v2, v3);
            } else {
                float* C = (float*)Cout + blockIdx.z * sC;
                *(float2*)(C + (size_t)m0 * ldc + n0)       = make_float2(v0, v1);
                *(float2*)(C + (size_t)(m0 + 8) * ldc + n0) = make_float2(v2, v3);
            }
        }
    }
}

// ---------------------------------------------------------------------------
// fp32 -> fp16 copy
// ---------------------------------------------------------------------------
__global__ __launch_bounds__(256)
void f2h_kernel(const float* __restrict__ src, __half* __restrict__ dst, size_t n4)
{
    const size_t stride = (size_t)gridDim.x * 256;
    for (size_t i = blockIdx.x * 256ull + threadIdx.x; i < n4; i += stride) {
        float4 v = ((const float4*)src)[i];
        ((__half2*)dst)[2 * i]     = __floats2half2_rn(v.x, v.y);
        ((__half2*)dst)[2 * i + 1] = __floats2half2_rn(v.z, v.w);
    }
}

// ---------------------------------------------------------------------------
// Tiled transpose with dtype conversion: out[c, r] = in[r, c]
// ---------------------------------------------------------------------------
template <typename TIN, typename TOUT>
__global__ __launch_bounds__(256)
void transpose_t(const TIN* __restrict__ in, TOUT* __restrict__ out,
                 int ld_in, int ld_out, size_t sIn, size_t sOut)
{
    __shared__ float tile[32][33];
    in  += blockIdx.z * sIn;
    out += blockIdx.z * sOut;
    const int r0 = blockIdx.y * 32;
    const int c0 = blockIdx.x * 32;
    const int tx = threadIdx.x;
    const int ty = threadIdx.y;
#pragma unroll
    for (int i = 0; i < 32; i += 8)
        tile[ty + i][tx] = (float)in[(size_t)(r0 + ty + i) * ld_in + c0 + tx];
    __syncthreads();
#pragma unroll
    for (int i = 0; i < 32; i += 8)
        out[(size_t)(c0 + ty + i) * ld_out + r0 + tx] = (TOUT)tile[tx][ty + i];
}

// ---------------------------------------------------------------------------
// Row softmax: reads fp32 S row, writes fp16 P row. rows = BATCH*NSEQ.
// ---------------------------------------------------------------------------
__global__ __launch_bounds__(256)
void softmax_kernel(const float* __restrict__ S, __half* __restrict__ P)
{
    const size_t row = blockIdx.x;
    const float2* p = (const float2*)(S + row * (size_t)NSEQ);
    __half2* q = (__half2*)(P + row * (size_t)NSEQ);
    const int tid = threadIdx.x;

    float2 v[8];
    float m = -INFINITY;
#pragma unroll
    for (int i = 0; i < 8; i++) {
        v[i] = p[tid + i * 256];
        m = fmaxf(m, fmaxf(v[i].x, v[i].y));
    }
#pragma unroll
    for (int o = 16; o > 0; o >>= 1)
        m = fmaxf(m, __shfl_xor_sync(0xFFFFFFFFu, m, o));

    __shared__ float redm[8];
    __shared__ float reds[8];
    if ((tid & 31) == 0) redm[tid >> 5] = m;
    __syncthreads();
    float mrow = redm[0];
#pragma unroll
    for (int w = 1; w < 8; w++) mrow = fmaxf(mrow, redm[w]);

    float s = 0.0f;
#pragma unroll
    for (int i = 0; i < 8; i++) {
        v[i].x = __expf(v[i].x - mrow);
        v[i].y = __expf(v[i].y - mrow);
        s += v[i].x + v[i].y;
    }
#pragma unroll
    for (int o = 16; o > 0; o >>= 1)
        s += __shfl_xor_sync(0xFFFFFFFFu, s, o);
    if ((tid & 31) == 0) reds[tid >> 5] = s;
    __syncthreads();
    float tot = 0.0f;
#pragma unroll
    for (int w = 0; w < 8; w++) tot += reds[w];
    const float inv = 1.0f / tot;

#pragma unroll
    for (int i = 0; i < 8; i++)
        q[tid + i * 256] = __floats2half2_rn(v[i].x * inv, v[i].y * inv);
}

// ---------------------------------------------------------------------------
extern "C" void kernel_launch(void* const* d_in, const int* in_sizes, int n_in,
                              void* d_out, int out_size)
{
    const float* x = (const float*)d_in[0];   // [4, 4096, 768]
    const float* W = (const float*)d_in[1];   // [768, 2304]
    const float* b = (const float*)d_in[2];   // [2304]
    float* out = (float*)d_out;               // [4, 4096, 768]

    __half *xh, *qkvh, *P, *Wth, *Vth;
    float *S;
    cudaGetSymbolAddress((void**)&xh, g_xh);
    cudaGetSymbolAddress((void**)&qkvh, g_qkvh);
    cudaGetSymbolAddress((void**)&S, g_S);
    cudaGetSymbolAddress((void**)&P, g_P);
    cudaGetSymbolAddress((void**)&Wth, g_Wth);
    cudaGetSymbolAddress((void**)&Vth, g_Vth);

    cudaFuncSetAttribute(hgemm_nt<true, true>,   cudaFuncAttributeMaxDynamicSharedMemorySize, GEMM_DYNSMEM);
    cudaFuncSetAttribute(hgemm_nt<false, false>, cudaFuncAttributeMaxDynamicSharedMemorySize, GEMM_DYNSMEM);

    const size_t qkvStride = (size_t)NSEQ * H3;
    const size_t sStride   = (size_t)NSEQ * NSEQ;
    const size_t oStride   = (size_t)NSEQ * DIMC;
    const size_t vtStride  = (size_t)DIMC * NSEQ;

    // 0a) xh = fp16(x)
    f2h_kernel<<<2048, 256>>>(x, xh, (size_t)BATCH * NSEQ * DIMC / 4);

    // 0b) Wth = fp16(W^T) : [768,2304] -> [2304,768]
    {
        dim3 grid(H3 / 32, DIMC / 32, 1);
        transpose_t<float, __half><<<grid, dim3(32, 8)>>>(W, Wth, H3, DIMC, 0, 0);
    }

    // 1) qkvh = fp16(xh @ Wth^T + b) : M=16384, N=2304, K=768
    {
        dim3 grid(H3 / 128, (BATCH * NSEQ) / 128, 1);
        hgemm_nt<true, true><<<grid, 128, GEMM_DYNSMEM>>>(
            xh, Wth, b, qkvh, DIMC, DIMC, DIMC, H3, 0, 0, 0, 1.0f);
    }

    // 2) Vth = V^T per batch : [4096,768] -> [768,4096]
    {
        dim3 grid(DIMC / 32, NSEQ / 32, BATCH);
        transpose_t<__half, __half><<<grid, dim3(32, 8)>>>(qkvh + 2 * DIMC, Vth, H3, NSEQ,
                                                           qkvStride, vtStride);
    }

    // 3) S = Q @ K^T * (1/sqrt(768)) per batch (fp32 out) : M=N=4096, K=768
    {
        dim3 grid(NSEQ / 128, NSEQ / 128, BATCH);
        const float alpha = 1.0f / sqrtf((float)DIMC);
        hgemm_nt<false, false><<<grid, 128, GEMM_DYNSMEM>>>(
            qkvh, qkvh + DIMC, nullptr, S, DIMC, H3, H3, NSEQ,
            qkvStride, qkvStride, sStride, alpha);
    }

    // 4) softmax rows of S -> fp16 P
    softmax_kernel<<<BATCH * NSEQ, 256>>>(S, P);

    // 5) out = P @ Vth^T per batch (fp32 out) : M=4096, N=768, K=4096
    {
        dim3 grid(DIMC / 128, NSEQ / 128, BATCH);
        hgemm_nt<false, false><<<grid, 128, GEMM_DYNSMEM>>>(
            P, Vth, nullptr, out, NSEQ, NSEQ, NSEQ, DIMC,
            sStride, vtStride, oStride, 1.0f);
    }
}